// round 12
// baseline (speedup 1.0000x reference)
#include <cuda_runtime.h>
#include <cstdint>

#define KNN 64
#define WPB 8
#define THREADS 256
#define QPW 4
#define QPB (WPB * QPW)          // 32 queries per block
#define POOLCAP 128
#define FULLMASK 0xFFFFFFFFu

typedef unsigned long long u64;

// Packed 2xfp32 ops (sm_100+). ptxas never emits these from C++ — PTX only.
#define PACK2(out, lo, hi) \
    asm("mov.b64 %0, {%1, %2};" : "=l"(out) : "f"(lo), "f"(hi))
#define ADD2(out, a, b) \
    asm("add.rn.f32x2 %0, %1, %2;" : "=l"(out) : "l"(a), "l"(b))
#define MUL2(out, a, b) \
    asm("mul.rn.f32x2 %0, %1, %2;" : "=l"(out) : "l"(a), "l"(b))
#define FMA2(out, a, b, c) \
    asm("fma.rn.f32x2 %0, %1, %2, %3;" : "=l"(out) : "l"(a), "l"(b), "l"(c))

__device__ __forceinline__ unsigned umax_(unsigned a, unsigned b) { return a > b ? a : b; }
__device__ __forceinline__ unsigned umin_(unsigned a, unsigned b) { return a < b ? a : b; }

// d2 (packed pair) via expansion: d2 = (sqc + sqq) - 2*dot(q,c). Op order
// matches the staged |c|^2 chain so the self-distance cancels to exactly +0.
#define DIST2(dout, CX, CY, CZ, CW, CQ, QX, QY, QZ, QW, SQ) do {           \
    u64 _t, _s;                                                            \
    MUL2(_t, QW, CW); FMA2(_t, QZ, CZ, _t);                                \
    FMA2(_t, QY, CY, _t); FMA2(_t, QX, CX, _t);                            \
    ADD2(_s, CQ, SQ);                                                      \
    FMA2(dout, _t, m2, _s);                                                \
} while (0)

// Insert packed pair (v0,v1) into sorted pair-slot (s0 <= s1): 6 IMNMX.
#define INS2(s0, s1, v0, v1) do {                                          \
    unsigned _lo = umin_(v0, v1), _hi = umax_(v0, v1);                     \
    s1 = umin_(umax_(s0, _lo), umin_(s1, _hi));                            \
    s0 = umin_(s0, _lo);                                                   \
} while (0)

// Per-query pass-1 body (token-pasted scalars; NO register arrays).
#define P1Q(q) do {                                                        \
    u64 _d0, _d1;                                                          \
    DIST2(_d0, cx.x, cy.x, cz.x, cw.x, cq.x, qx##q, qy##q, qz##q, qw##q, qs##q); \
    DIST2(_d1, cx.y, cy.y, cz.y, cw.y, cq.y, qx##q, qy##q, qz##q, qw##q, qs##q); \
    INS2(Ta0##q, Ta1##q, (unsigned)_d0, (unsigned)(_d0 >> 32));            \
    INS2(Tb0##q, Tb1##q, (unsigned)_d1, (unsigned)(_d1 >> 32));            \
} while (0)

// Per-query pass-2 body.
#define P2Q(q) do {                                                        \
    u64 _d0, _d1;                                                          \
    DIST2(_d0, cx.x, cy.x, cz.x, cw.x, cq.x, qx##q, qy##q, qz##q, qw##q, qs##q); \
    DIST2(_d1, cx.y, cy.y, cz.y, cw.y, cq.y, qx##q, qy##q, qz##q, qw##q, qs##q); \
    unsigned _v0 = (unsigned)_d0, _v1 = (unsigned)(_d0 >> 32);             \
    unsigned _v2 = (unsigned)_d1, _v3 = (unsigned)(_d1 >> 32);             \
    if (_v0 < tau##q) { int _p = atomicAdd(cnt##q, 1);                     \
        if (_p < POOLCAP) pool##q[_p] = (((u64)_v0) << 32) | (unsigned)(j + 0); } \
    if (_v1 < tau##q) { int _p = atomicAdd(cnt##q, 1);                     \
        if (_p < POOLCAP) pool##q[_p] = (((u64)_v1) << 32) | (unsigned)(j + 1); } \
    if (_v2 < tau##q) { int _p = atomicAdd(cnt##q, 1);                     \
        if (_p < POOLCAP) pool##q[_p] = (((u64)_v2) << 32) | (unsigned)(j + 2); } \
    if (_v3 < tau##q) { int _p = atomicAdd(cnt##q, 1);                     \
        if (_p < POOLCAP) pool##q[_p] = (((u64)_v3) << 32) | (unsigned)(j + 3); } \
} while (0)

// tau = (64th smallest of the warp's 128 collected bit-values) + 1.
// Collected set is a subset of all candidate d2 bits -> tau upper-bounds the
// true 64th-smallest distance, so the pass-2 filter keeps the whole top-64.
__device__ __forceinline__ unsigned find_tau4(unsigned m0, unsigned s0,
                                              unsigned m1, unsigned s1)
{
    unsigned lo = __reduce_min_sync(FULLMASK, umin_(m0, m1));       // count(<lo)==0
    unsigned hi = __reduce_max_sync(FULLMASK, umax_(s0, s1)) + 1u;  // count(<hi)==128
    while (lo + 1u < hi) {
        unsigned mid = lo + ((hi - lo) >> 1);
        unsigned c4 = (unsigned)(m0 < mid) + (unsigned)(s0 < mid)
                    + (unsigned)(m1 < mid) + (unsigned)(s1 < mid);
        c4 = __reduce_add_sync(FULLMASK, c4);
        if (c4 >= 64u) hi = mid; else lo = mid;
    }
    return hi;
}

// Exact rank scatter of pool[0..cnt) (distinct u64 keys) -> top-64 to output.
template <int R>
__device__ __forceinline__ void rank_scatter(const u64* pool, int cnt,
                                             float* out_idx, float* out_dist,
                                             size_t obase, int gbase, int lane)
{
    u64 k[R];
    int r[R];
#pragma unroll
    for (int i = 0; i < R; i++) {
        int e = lane + 32 * i;
        k[i] = (e < cnt) ? pool[e] : ~0ULL;
        r[i] = 0;
    }
    for (int j = 0; j < cnt; j++) {
        u64 kj = pool[j];                            // broadcast LDS
#pragma unroll
        for (int i = 0; i < R; i++) r[i] += (kj < k[i]) ? 1 : 0;
    }
#pragma unroll
    for (int i = 0; i < R; i++) {
        int e = lane + 32 * i;
        if (e < cnt && r[i] < KNN) {
            out_idx [obase + r[i]] = (float)((int)(unsigned)k[i] + gbase);
            out_dist[obase + r[i]] = fmaxf(__uint_as_float((unsigned)(k[i] >> 32)), 0.0f);
        }
    }
}

// Exact bound-tournament fallback (pathological pool overflow only).
__device__ __forceinline__ void exact_tournament(const float* sx, const float* sy,
                                                 const float* sz, const float* sw,
                                                 const float* sq,
                                                 float qx, float qy, float qz, float qw,
                                                 float sqq, int S,
                                                 float* out_idx, float* out_dist,
                                                 size_t obase, int gbase, int lane)
{
    u64 bound = 0ULL;
    const int iters = S >> 5;
#pragma unroll 1
    for (int kk = 0; kk < KNN; kk++) {
        u64 best = ~0ULL;
        for (int m = 0; m < iters; m++) {
            const int j = (m << 5) + lane;
            float dot = fmaf(qx, sx[j], fmaf(qy, sy[j], fmaf(qz, sz[j], qw * sw[j])));
            float d2 = fmaf(dot, -2.0f, sq[j] + sqq);
            u64 key = (((u64)__float_as_uint(d2)) << 32) | (unsigned)j;
            if (key >= bound && key < best) best = key;
        }
        unsigned hb = (unsigned)(best >> 32);
        unsigned mh = __reduce_min_sync(FULLMASK, hb);
        unsigned lb = (hb == mh) ? (unsigned)best : 0xFFFFFFFFu;
        unsigned ml = __reduce_min_sync(FULLMASK, lb);
        if (lane == 0) {
            out_idx [obase + kk] = (float)((int)ml + gbase);
            out_dist[obase + kk] = fmaxf(__uint_as_float(mh), 0.0f);
        }
        bound = ((((u64)mh) << 32) | ml) + 1ULL;
    }
}

__device__ __forceinline__ void finish_query(const u64* pool, int cnt,
                                             const float* sx, const float* sy,
                                             const float* sz, const float* sw,
                                             const float* sq,
                                             float qx, float qy, float qz, float qw,
                                             float sqq, int S,
                                             float* out_idx, float* out_dist,
                                             size_t obase, int gbase, int lane)
{
    if (cnt <= 96)
        rank_scatter<3>(pool, cnt, out_idx, out_dist, obase, gbase, lane);
    else if (cnt <= POOLCAP)
        rank_scatter<4>(pool, cnt, out_idx, out_dist, obase, gbase, lane);
    else
        exact_tournament(sx, sy, sz, sw, sq, qx, qy, qz, qw, sqq, S,
                         out_idx, out_dist, obase, gbase, lane);
}

__global__ void __launch_bounds__(THREADS, 2)
knn_q4s_kernel(const float4* __restrict__ coords,
               float* __restrict__ out_idx,
               float* __restrict__ out_dist,
               int S)
{
    extern __shared__ unsigned char smem_raw[];
    float* sx = reinterpret_cast<float*>(smem_raw);
    float* sy = sx + S;
    float* sz = sy + S;
    float* sw = sz + S;
    float* sq = sw + S;
    u64* poolBase = reinterpret_cast<u64*>(smem_raw + (size_t)S * 5 * sizeof(float));
    int* cntBase = reinterpret_cast<int*>(poolBase + (size_t)WPB * QPW * POOLCAP);

    const int tid  = threadIdx.x;
    const int warp = tid >> 5;
    const int lane = tid & 31;

    const int bps = S / QPB;
    const int seg = blockIdx.x / bps;
    const int qloc = (blockIdx.x % bps) * QPB + warp * QPW;  // queries qloc..qloc+3
    const int gbase = seg * S;

    // ---- stage SoA coords + |c|^2; zero counters ----
    const float4* segc = coords + (size_t)gbase;
    for (int i = tid; i < S; i += THREADS) {
        float4 c = segc[i];
        sx[i] = c.x; sy[i] = c.y; sz[i] = c.z; sw[i] = c.w;
        sq[i] = fmaf(c.x, c.x, fmaf(c.y, c.y, fmaf(c.z, c.z, c.w * c.w)));
    }
    if (tid < WPB * QPW) cntBase[tid] = 0;
    __syncthreads();

    // Scalar query constants (kept for the fallback path).
    const float fx0 = sx[qloc+0], fy0 = sy[qloc+0], fz0 = sz[qloc+0], fw0 = sw[qloc+0], fs0 = sq[qloc+0];
    const float fx1 = sx[qloc+1], fy1 = sy[qloc+1], fz1 = sz[qloc+1], fw1 = sw[qloc+1], fs1 = sq[qloc+1];
    const float fx2 = sx[qloc+2], fy2 = sy[qloc+2], fz2 = sz[qloc+2], fw2 = sw[qloc+2], fs2 = sq[qloc+2];
    const float fx3 = sx[qloc+3], fy3 = sy[qloc+3], fz3 = sz[qloc+3], fw3 = sw[qloc+3], fs3 = sq[qloc+3];

    u64 qx0, qy0, qz0, qw0, qs0, qx1, qy1, qz1, qw1, qs1;
    u64 qx2, qy2, qz2, qw2, qs2, qx3, qy3, qz3, qw3, qs3, m2;
    PACK2(qx0, fx0, fx0); PACK2(qy0, fy0, fy0); PACK2(qz0, fz0, fz0); PACK2(qw0, fw0, fw0); PACK2(qs0, fs0, fs0);
    PACK2(qx1, fx1, fx1); PACK2(qy1, fy1, fy1); PACK2(qz1, fz1, fz1); PACK2(qw1, fw1, fw1); PACK2(qs1, fs1, fs1);
    PACK2(qx2, fx2, fx2); PACK2(qy2, fy2, fy2); PACK2(qz2, fz2, fz2); PACK2(qw2, fw2, fw2); PACK2(qs2, fs2, fs2);
    PACK2(qx3, fx3, fx3); PACK2(qy3, fy3, fy3); PACK2(qz3, fz3, fz3); PACK2(qw3, fw3, fw3); PACK2(qs3, fs3, fs3);
    PACK2(m2, -2.0f, -2.0f);

    const int iters = S >> 7;               // 32 iters, 4 candidates/lane/iter
    const int lane4 = lane << 2;

    // ---- pass 1: top-2 per pair-stream (2 streams per lane per query) ----
    unsigned Ta00 = ~0u, Ta10 = ~0u, Tb00 = ~0u, Tb10 = ~0u;
    unsigned Ta01 = ~0u, Ta11 = ~0u, Tb01 = ~0u, Tb11 = ~0u;
    unsigned Ta02 = ~0u, Ta12 = ~0u, Tb02 = ~0u, Tb12 = ~0u;
    unsigned Ta03 = ~0u, Ta13 = ~0u, Tb03 = ~0u, Tb13 = ~0u;

#pragma unroll 2
    for (int m = 0; m < iters; m++) {
        const int j = (m << 7) + lane4;
        ulonglong2 cx = *reinterpret_cast<const ulonglong2*>(sx + j);
        ulonglong2 cy = *reinterpret_cast<const ulonglong2*>(sy + j);
        ulonglong2 cz = *reinterpret_cast<const ulonglong2*>(sz + j);
        ulonglong2 cw = *reinterpret_cast<const ulonglong2*>(sw + j);
        ulonglong2 cq = *reinterpret_cast<const ulonglong2*>(sq + j);
        P1Q(0); P1Q(1); P1Q(2); P1Q(3);
    }

    const unsigned tau0 = find_tau4(Ta00, Ta10, Tb00, Tb10);
    const unsigned tau1 = find_tau4(Ta01, Ta11, Tb01, Tb11);
    const unsigned tau2 = find_tau4(Ta02, Ta12, Tb02, Tb12);
    const unsigned tau3 = find_tau4(Ta03, Ta13, Tb03, Tb13);

    // ---- pass 2: append all candidates with db < tau to per-query pools ----
    u64* pool0 = poolBase + (size_t)(warp * QPW) * POOLCAP;
    u64* pool1 = pool0 + POOLCAP;
    u64* pool2 = pool1 + POOLCAP;
    u64* pool3 = pool2 + POOLCAP;
    int* cnt0 = cntBase + warp * QPW;
    int* cnt1 = cnt0 + 1;
    int* cnt2 = cnt0 + 2;
    int* cnt3 = cnt0 + 3;

#pragma unroll 2
    for (int m = 0; m < iters; m++) {
        const int j = (m << 7) + lane4;
        ulonglong2 cx = *reinterpret_cast<const ulonglong2*>(sx + j);
        ulonglong2 cy = *reinterpret_cast<const ulonglong2*>(sy + j);
        ulonglong2 cz = *reinterpret_cast<const ulonglong2*>(sz + j);
        ulonglong2 cw = *reinterpret_cast<const ulonglong2*>(sw + j);
        ulonglong2 cq = *reinterpret_cast<const ulonglong2*>(sq + j);
        P2Q(0); P2Q(1); P2Q(2); P2Q(3);
    }
    __syncwarp();

    // ---- per query: exact rank scatter (or rare exact fallback) ----
    const size_t ob0 = (size_t)(gbase + qloc) * KNN;
    finish_query(pool0, *cnt0, sx, sy, sz, sw, sq, fx0, fy0, fz0, fw0, fs0, S,
                 out_idx, out_dist, ob0,           gbase, lane);
    finish_query(pool1, *cnt1, sx, sy, sz, sw, sq, fx1, fy1, fz1, fw1, fs1, S,
                 out_idx, out_dist, ob0 + KNN,     gbase, lane);
    finish_query(pool2, *cnt2, sx, sy, sz, sw, sq, fx2, fy2, fz2, fw2, fs2, S,
                 out_idx, out_dist, ob0 + 2 * KNN, gbase, lane);
    finish_query(pool3, *cnt3, sx, sy, sz, sw, sq, fx3, fy3, fz3, fw3, fs3, S,
                 out_idx, out_dist, ob0 + 3 * KNN, gbase, lane);
}

extern "C" void kernel_launch(void* const* d_in, const int* in_sizes, int n_in,
                              void* d_out, int out_size)
{
    // metadata order: K (scalar), coordinates [N*4 f32], row_splits [B+1 i32]
    const float4* coords = (const float4*)d_in[1];
    const int n_coord_floats = in_sizes[1];
    const int B = in_sizes[2] - 1;
    const int N = n_coord_floats / 4;   // D = 4
    const int S = N / B;                // equal-sized segments (4096)

    float* out = (float*)d_out;
    float* out_idx  = out;
    float* out_dist = out + (size_t)N * KNN;

    size_t smem = (size_t)S * 5 * sizeof(float)
                + (size_t)WPB * QPW * POOLCAP * sizeof(u64)
                + (size_t)WPB * QPW * sizeof(int);

    cudaFuncSetAttribute(knn_q4s_kernel,
                         cudaFuncAttributeMaxDynamicSharedMemorySize, (int)smem);
    cudaFuncSetAttribute(knn_q4s_kernel,
                         cudaFuncAttributePreferredSharedMemoryCarveout, 100);

    dim3 block(THREADS);
    dim3 grid(N / QPB);
    knn_q4s_kernel<<<grid, block, smem>>>(coords, out_idx, out_dist, S);
}

// round 13
// speedup vs baseline: 1.1646x; 1.1646x over previous
#include <cuda_runtime.h>
#include <cstdint>

#define KNN 64
#define WPB 16
#define THREADS 512
#define QPB (WPB * 2)            // 32 queries per block
#define POOLCAP 120
#define PCAP2 124                // POOLCAP + 4 pad entries (uint4-aligned)
#define FULLMASK 0xFFFFFFFFu

typedef unsigned long long u64;

// Packed 2xfp32 ops (sm_100+). ptxas never emits these from C++ — PTX only.
#define PACK2(out, lo, hi) \
    asm("mov.b64 %0, {%1, %2};" : "=l"(out) : "f"(lo), "f"(hi))
#define ADD2(out, a, b) \
    asm("add.rn.f32x2 %0, %1, %2;" : "=l"(out) : "l"(a), "l"(b))
#define MUL2(out, a, b) \
    asm("mul.rn.f32x2 %0, %1, %2;" : "=l"(out) : "l"(a), "l"(b))
#define FMA2(out, a, b, c) \
    asm("fma.rn.f32x2 %0, %1, %2, %3;" : "=l"(out) : "l"(a), "l"(b), "l"(c))

__device__ __forceinline__ unsigned umax_(unsigned a, unsigned b) { return a > b ? a : b; }
__device__ __forceinline__ unsigned umin_(unsigned a, unsigned b) { return a < b ? a : b; }

// d2 (packed pair) via expansion: d2 = (sqc + sqq) - 2*dot(q,c). Op order
// matches the staged |c|^2 chain so the self-distance cancels to exactly +0.
#define DIST2(dout, CX, CY, CZ, CW, CQ, QX, QY, QZ, QW, SQ) do {           \
    u64 _t, _s;                                                            \
    MUL2(_t, QW, CW); FMA2(_t, QZ, CZ, _t);                                \
    FMA2(_t, QY, CY, _t); FMA2(_t, QX, CX, _t);                            \
    ADD2(_s, CQ, SQ);                                                      \
    FMA2(dout, _t, m2, _s);                                                \
} while (0)

// Insert packed pair (v0,v1) into sorted pair-slot (s0 <= s1): 6 IMNMX.
#define INS2(s0, s1, v0, v1) do {                                          \
    unsigned _lo = umin_(v0, v1), _hi = umax_(v0, v1);                     \
    s1 = umin_(umax_(s0, _lo), umin_(s1, _hi));                            \
    s0 = umin_(s0, _lo);                                                   \
} while (0)

// tau = (64th smallest of the warp's 128 collected bit-values) + 1.
// Collected set is a subset of all candidate d2 bits -> tau upper-bounds the
// true 64th-smallest distance, so the pass-2 filter keeps the whole top-64.
__device__ __forceinline__ unsigned find_tau4(unsigned m0, unsigned s0,
                                              unsigned m1, unsigned s1)
{
    unsigned lo = __reduce_min_sync(FULLMASK, umin_(m0, m1));       // count(<lo)==0
    unsigned hi = __reduce_max_sync(FULLMASK, umax_(s0, s1)) + 1u;  // count(<hi)==128
    while (lo + 1u < hi) {
        unsigned mid = lo + ((hi - lo) >> 1);
        unsigned c4 = (unsigned)(m0 < mid) + (unsigned)(s0 < mid)
                    + (unsigned)(m1 < mid) + (unsigned)(s1 < mid);
        c4 = __reduce_add_sync(FULLMASK, c4);
        if (c4 >= 64u) hi = mid; else lo = mid;
    }
    return hi;
}

// Exact rank scatter over split pools. Ranks by u32 d2-bits (uint4 inner
// loop); exactness is verified by the rank-sum permutation check, with an
// exact (d2, idx) lexicographic re-rank on the (rare) tie.
template <int R>
__device__ __forceinline__ void rank_scatter(const unsigned* pD, const unsigned* pI,
                                             int cnt,
                                             float* out_idx, float* out_dist,
                                             size_t obase, int gbase, int lane)
{
    unsigned kd[R], ki[R];
    int r[R];
#pragma unroll
    for (int i = 0; i < R; i++) {
        int e = lane + 32 * i;
        bool v = e < cnt;
        kd[i] = v ? pD[e] : 0xFFFFFFFFu;
        ki[i] = v ? pI[e] : 0u;
        r[i] = 0;
    }
    const int cntP = (cnt + 3) & ~3;
    for (int j = 0; j < cntP; j += 4) {
        uint4 d = *reinterpret_cast<const uint4*>(pD + j);   // LDS.128 broadcast
#pragma unroll
        for (int i = 0; i < R; i++) {
            r[i] += (int)(d.x < kd[i]) + (int)(d.y < kd[i])
                  + (int)(d.z < kd[i]) + (int)(d.w < kd[i]);
        }
    }
    // Permutation check: any d2 tie strictly lowers the rank sum.
    int s = 0;
#pragma unroll
    for (int i = 0; i < R; i++)
        if (lane + 32 * i < cnt) s += r[i];
    s = __reduce_add_sync(FULLMASK, s);
    if (s != (cnt * (cnt - 1)) / 2) {
        // rare: exact lexicographic (d2, idx) re-rank
#pragma unroll
        for (int i = 0; i < R; i++) r[i] = 0;
        for (int j = 0; j < cnt; j++) {
            unsigned dj = pD[j], ij = pI[j];
#pragma unroll
            for (int i = 0; i < R; i++)
                r[i] += (int)((dj < kd[i]) || (dj == kd[i] && ij < ki[i]));
        }
    }
#pragma unroll
    for (int i = 0; i < R; i++) {
        int e = lane + 32 * i;
        if (e < cnt && r[i] < KNN) {
            out_idx [obase + r[i]] = (float)((int)ki[i] + gbase);
            out_dist[obase + r[i]] = fmaxf(__uint_as_float(kd[i]), 0.0f);
        }
    }
}

// Exact bound-tournament fallback (pathological pool overflow only).
__device__ __forceinline__ void exact_tournament(const float* sx, const float* sy,
                                                 const float* sz, const float* sw,
                                                 const float* sq,
                                                 float qx, float qy, float qz, float qw,
                                                 float sqq, int S,
                                                 float* out_idx, float* out_dist,
                                                 size_t obase, int gbase, int lane)
{
    u64 bound = 0ULL;
    const int iters = S >> 5;
#pragma unroll 1
    for (int kk = 0; kk < KNN; kk++) {
        u64 best = ~0ULL;
        for (int m = 0; m < iters; m++) {
            const int j = (m << 5) + lane;
            float dot = fmaf(qx, sx[j], fmaf(qy, sy[j], fmaf(qz, sz[j], qw * sw[j])));
            float d2 = fmaf(dot, -2.0f, sq[j] + sqq);
            u64 key = (((u64)__float_as_uint(d2)) << 32) | (unsigned)j;
            if (key >= bound && key < best) best = key;
        }
        unsigned hb = (unsigned)(best >> 32);
        unsigned mh = __reduce_min_sync(FULLMASK, hb);
        unsigned lb = (hb == mh) ? (unsigned)best : 0xFFFFFFFFu;
        unsigned ml = __reduce_min_sync(FULLMASK, lb);
        if (lane == 0) {
            out_idx [obase + kk] = (float)((int)ml + gbase);
            out_dist[obase + kk] = fmaxf(__uint_as_float(mh), 0.0f);
        }
        bound = ((((u64)mh) << 32) | ml) + 1ULL;
    }
}

__global__ void __launch_bounds__(THREADS, 2)
knn_u32sort_kernel(const float4* __restrict__ coords,
                   float* __restrict__ out_idx,
                   float* __restrict__ out_dist,
                   int S)
{
    extern __shared__ unsigned char smem_raw[];
    float* sx = reinterpret_cast<float*>(smem_raw);
    float* sy = sx + S;
    float* sz = sy + S;
    float* sw = sz + S;
    float* sq = sw + S;
    unsigned* poolD = reinterpret_cast<unsigned*>(smem_raw + (size_t)S * 5 * sizeof(float));
    unsigned* poolI = poolD + (size_t)WPB * 2 * PCAP2;
    int* cntBase = reinterpret_cast<int*>(poolI + (size_t)WPB * 2 * PCAP2);

    const int tid  = threadIdx.x;
    const int warp = tid >> 5;
    const int lane = tid & 31;

    const int bps = S / QPB;
    const int seg = blockIdx.x / bps;
    const int qloc = (blockIdx.x % bps) * QPB + warp * 2;   // queries qloc, qloc+1
    const int gbase = seg * S;

    // ---- stage SoA coords + |c|^2; zero counters ----
    const float4* segc = coords + (size_t)gbase;
    for (int i = tid; i < S; i += THREADS) {
        float4 c = segc[i];
        sx[i] = c.x; sy[i] = c.y; sz[i] = c.z; sw[i] = c.w;
        sq[i] = fmaf(c.x, c.x, fmaf(c.y, c.y, fmaf(c.z, c.z, c.w * c.w)));
    }
    if (tid < WPB * 2) cntBase[tid] = 0;
    __syncthreads();

    const float qax = sx[qloc],     qay = sy[qloc],     qaz = sz[qloc],     qaw = sw[qloc];
    const float qbx = sx[qloc + 1], qby = sy[qloc + 1], qbz = sz[qloc + 1], qbw = sw[qloc + 1];
    const float sqa = sq[qloc], sqb = sq[qloc + 1];

    u64 qAx2, qAy2, qAz2, qAw2, qBx2, qBy2, qBz2, qBw2, sqA2, sqB2, m2;
    PACK2(qAx2, qax, qax); PACK2(qAy2, qay, qay); PACK2(qAz2, qaz, qaz); PACK2(qAw2, qaw, qaw);
    PACK2(qBx2, qbx, qbx); PACK2(qBy2, qby, qby); PACK2(qBz2, qbz, qbz); PACK2(qBw2, qbw, qbw);
    PACK2(sqA2, sqa, sqa); PACK2(sqB2, sqb, sqb);
    PACK2(m2, -2.0f, -2.0f);

    const int iters = S >> 7;               // 32 iters, 4 candidates/lane/iter
    const int lane4 = lane << 2;

    // ---- pass 1: top-2 per pair-stream (2 streams per lane per query) ----
    unsigned A00 = ~0u, A01 = ~0u, A10 = ~0u, A11 = ~0u;
    unsigned B00 = ~0u, B01 = ~0u, B10 = ~0u, B11 = ~0u;

#pragma unroll 2
    for (int m = 0; m < iters; m++) {
        const int j = (m << 7) + lane4;
        ulonglong2 cx = *reinterpret_cast<const ulonglong2*>(sx + j);
        ulonglong2 cy = *reinterpret_cast<const ulonglong2*>(sy + j);
        ulonglong2 cz = *reinterpret_cast<const ulonglong2*>(sz + j);
        ulonglong2 cw = *reinterpret_cast<const ulonglong2*>(sw + j);
        ulonglong2 cq = *reinterpret_cast<const ulonglong2*>(sq + j);

        u64 dA0, dA1, dB0, dB1;
        DIST2(dA0, cx.x, cy.x, cz.x, cw.x, cq.x, qAx2, qAy2, qAz2, qAw2, sqA2);
        DIST2(dA1, cx.y, cy.y, cz.y, cw.y, cq.y, qAx2, qAy2, qAz2, qAw2, sqA2);
        DIST2(dB0, cx.x, cy.x, cz.x, cw.x, cq.x, qBx2, qBy2, qBz2, qBw2, sqB2);
        DIST2(dB1, cx.y, cy.y, cz.y, cw.y, cq.y, qBx2, qBy2, qBz2, qBw2, sqB2);

        INS2(A00, A01, (unsigned)dA0, (unsigned)(dA0 >> 32));
        INS2(A10, A11, (unsigned)dA1, (unsigned)(dA1 >> 32));
        INS2(B00, B01, (unsigned)dB0, (unsigned)(dB0 >> 32));
        INS2(B10, B11, (unsigned)dB1, (unsigned)(dB1 >> 32));
    }

    const unsigned tauA = find_tau4(A00, A01, A10, A11);
    const unsigned tauB = find_tau4(B00, B01, B10, B11);

    // ---- pass 2: append (d2bits, idx) to split per-query pools ----
    unsigned* pDA = poolD + (size_t)(warp * 2) * PCAP2;
    unsigned* pDB = pDA + PCAP2;
    unsigned* pIA = poolI + (size_t)(warp * 2) * PCAP2;
    unsigned* pIB = pIA + PCAP2;
    int* cntA = cntBase + warp * 2;
    int* cntB = cntA + 1;

#pragma unroll 2
    for (int m = 0; m < iters; m++) {
        const int j = (m << 7) + lane4;
        ulonglong2 cx = *reinterpret_cast<const ulonglong2*>(sx + j);
        ulonglong2 cy = *reinterpret_cast<const ulonglong2*>(sy + j);
        ulonglong2 cz = *reinterpret_cast<const ulonglong2*>(sz + j);
        ulonglong2 cw = *reinterpret_cast<const ulonglong2*>(sw + j);
        ulonglong2 cq = *reinterpret_cast<const ulonglong2*>(sq + j);

        u64 dA0, dA1, dB0, dB1;
        DIST2(dA0, cx.x, cy.x, cz.x, cw.x, cq.x, qAx2, qAy2, qAz2, qAw2, sqA2);
        DIST2(dA1, cx.y, cy.y, cz.y, cw.y, cq.y, qAx2, qAy2, qAz2, qAw2, sqA2);
        DIST2(dB0, cx.x, cy.x, cz.x, cw.x, cq.x, qBx2, qBy2, qBz2, qBw2, sqB2);
        DIST2(dB1, cx.y, cy.y, cz.y, cw.y, cq.y, qBx2, qBy2, qBz2, qBw2, sqB2);

        unsigned a0 = (unsigned)dA0, a1 = (unsigned)(dA0 >> 32);
        unsigned a2 = (unsigned)dA1, a3 = (unsigned)(dA1 >> 32);
        unsigned b0 = (unsigned)dB0, b1 = (unsigned)(dB0 >> 32);
        unsigned b2 = (unsigned)dB1, b3 = (unsigned)(dB1 >> 32);

        if (a0 < tauA) { int p = atomicAdd(cntA, 1);
            if (p < POOLCAP) { pDA[p] = a0; pIA[p] = (unsigned)(j + 0); } }
        if (a1 < tauA) { int p = atomicAdd(cntA, 1);
            if (p < POOLCAP) { pDA[p] = a1; pIA[p] = (unsigned)(j + 1); } }
        if (a2 < tauA) { int p = atomicAdd(cntA, 1);
            if (p < POOLCAP) { pDA[p] = a2; pIA[p] = (unsigned)(j + 2); } }
        if (a3 < tauA) { int p = atomicAdd(cntA, 1);
            if (p < POOLCAP) { pDA[p] = a3; pIA[p] = (unsigned)(j + 3); } }
        if (b0 < tauB) { int p = atomicAdd(cntB, 1);
            if (p < POOLCAP) { pDB[p] = b0; pIB[p] = (unsigned)(j + 0); } }
        if (b1 < tauB) { int p = atomicAdd(cntB, 1);
            if (p < POOLCAP) { pDB[p] = b1; pIB[p] = (unsigned)(j + 1); } }
        if (b2 < tauB) { int p = atomicAdd(cntB, 1);
            if (p < POOLCAP) { pDB[p] = b2; pIB[p] = (unsigned)(j + 2); } }
        if (b3 < tauB) { int p = atomicAdd(cntB, 1);
            if (p < POOLCAP) { pDB[p] = b3; pIB[p] = (unsigned)(j + 3); } }
    }
    __syncwarp();

    const int cA = *cntA;
    const int cB = *cntB;

    // pad pools to a uint4 boundary with MAX keys (never beat real entries)
    if (lane < 4) {
        if (cA <= POOLCAP) pDA[cA + lane] = 0xFFFFFFFFu;
        if (cB <= POOLCAP) pDB[cB + lane] = 0xFFFFFFFFu;
    }
    __syncwarp();

    // ---- exact rank scatter to output, per query ----
    const size_t obA = (size_t)(gbase + qloc) * KNN;
    const size_t obB = obA + KNN;

    if (cA <= 96)           rank_scatter<3>(pDA, pIA, cA, out_idx, out_dist, obA, gbase, lane);
    else if (cA <= POOLCAP) rank_scatter<4>(pDA, pIA, cA, out_idx, out_dist, obA, gbase, lane);
    else exact_tournament(sx, sy, sz, sw, sq, qax, qay, qaz, qaw, sqa, S,
                          out_idx, out_dist, obA, gbase, lane);

    if (cB <= 96)           rank_scatter<3>(pDB, pIB, cB, out_idx, out_dist, obB, gbase, lane);
    else if (cB <= POOLCAP) rank_scatter<4>(pDB, pIB, cB, out_idx, out_dist, obB, gbase, lane);
    else exact_tournament(sx, sy, sz, sw, sq, qbx, qby, qbz, qbw, sqb, S,
                          out_idx, out_dist, obB, gbase, lane);
}

extern "C" void kernel_launch(void* const* d_in, const int* in_sizes, int n_in,
                              void* d_out, int out_size)
{
    // metadata order: K (scalar), coordinates [N*4 f32], row_splits [B+1 i32]
    const float4* coords = (const float4*)d_in[1];
    const int n_coord_floats = in_sizes[1];
    const int B = in_sizes[2] - 1;
    const int N = n_coord_floats / 4;   // D = 4
    const int S = N / B;                // equal-sized segments (4096)

    float* out = (float*)d_out;
    float* out_idx  = out;
    float* out_dist = out + (size_t)N * KNN;

    size_t smem = (size_t)S * 5 * sizeof(float)
                + (size_t)WPB * 2 * PCAP2 * 2 * sizeof(unsigned)
                + (size_t)WPB * 2 * sizeof(int);

    cudaFuncSetAttribute(knn_u32sort_kernel,
                         cudaFuncAttributeMaxDynamicSharedMemorySize, (int)smem);
    cudaFuncSetAttribute(knn_u32sort_kernel,
                         cudaFuncAttributePreferredSharedMemoryCarveout, 100);

    dim3 block(THREADS);
    dim3 grid(N / QPB);
    knn_u32sort_kernel<<<grid, block, smem>>>(coords, out_idx, out_dist, S);
}